// round 1
// baseline (speedup 1.0000x reference)
#include <cuda_runtime.h>
#include <math.h>

#define NN 20000
#define EE 320000
#define DD 128
#define HH 8
#define PP 16
#define GG 64
#define WIDTHF (5.0f/63.0f)
#define LN_EPS 1e-5f

// ---------------- scratch (device globals; no allocation allowed) ----------
__device__ float g_q[(size_t)EE*DD];      // layernormed edge features
__device__ float g_v[(size_t)EE*DD];      // v_vec
__device__ float g_logit[(size_t)EE*HH];  // logits, then exp-numerators
__device__ float g_C[EE];                 // cosine cutoff per edge
__device__ float g_qvec[(size_t)NN*DD];   // node-level q
__device__ float g_h2[(size_t)NN*DD];     // aggregated he
__device__ int   g_mmax[(size_t)NN*HH];   // segment max (monotone-int encoded)
__device__ float g_ssum[(size_t)NN*HH];   // segment sum of a*C

// monotone float<->int encoding for atomicMax on signed int
__device__ __forceinline__ int fenc(float f) {
    int i = __float_as_int(f);
    return (i < 0) ? (i ^ 0x7fffffff) : i;
}
__device__ __forceinline__ float fdec(int i) {
    return __int_as_float((i < 0) ? (i ^ 0x7fffffff) : i);
}

// ---------------- init segment buffers ------------------------------------
__global__ void k_init() {
    int t = blockIdx.x * blockDim.x + threadIdx.x;
    if (t < NN * DD) g_h2[t] = 0.0f;
    if (t < NN * HH) {
        g_mmax[t] = fenc(__int_as_float(0xff800000)); // -inf
        g_ssum[t] = 0.0f;
    }
}

// ---------------- K1: distances, RBF filter GEMM, cutoff, q = LN(W*h1[dst]+t)
// block: 256 threads, 64 edges. E % 64 == 0 (320000/64 = 5000).
__global__ __launch_bounds__(256) void k_edge_filter(
    const float* __restrict__ pos, const float* __restrict__ h1,
    const float* __restrict__ t_in, const float* __restrict__ fw,
    const float* __restrict__ fb, const float* __restrict__ lng,
    const float* __restrict__ lnb, const int* __restrict__ src,
    const int* __restrict__ dst, float* __restrict__ outW)
{
    extern __shared__ float sm[];
    float* s_fw = sm;                 // [GG][DD] 32KB
    float* s_f2 = sm + GG * DD;       // [64][GG] 16KB
    __shared__ float s_r[64], s_C[64];
    __shared__ int s_dst[64];

    const int tid = threadIdx.x;
    const int base = blockIdx.x * 64;

    // stage filter weights
    for (int i = tid; i < GG * DD / 4; i += 256)
        ((float4*)s_fw)[i] = ((const float4*)fw)[i];

    // per-edge geometry
    if (tid < 64) {
        int e = base + tid;
        int sI = src[e], dI = dst[e];
        float dx = pos[dI * 3 + 0] - pos[sI * 3 + 0];
        float dy = pos[dI * 3 + 1] - pos[sI * 3 + 1];
        float dz = pos[dI * 3 + 2] - pos[sI * 3 + 2];
        float r = sqrtf(dx * dx + dy * dy + dz * dz);
        float C = (r < 5.0f) ? 0.5f * (cospif(r * 0.2f) + 1.0f) : 0.0f;
        s_r[tid] = r; s_C[tid] = C; s_dst[tid] = dI;
        g_C[e] = C;
    }
    __syncthreads();

    // 2*gaussian - 1 per (edge, g); skip exp when negligible (<1.4e-14)
    const float alpha = -0.5f / (WIDTHF * WIDTHF);
    for (int idx = tid; idx < 64 * GG; idx += 256) {
        int e = idx >> 6, g = idx & 63;
        float diff = s_r[e] - (float)g * WIDTHF;
        float f2 = (fabsf(diff) < 8.0f * WIDTHF)
                       ? 2.0f * __expf(alpha * diff * diff) - 1.0f
                       : -1.0f;
        s_f2[e * GG + g] = f2;
    }
    __syncthreads();

    const int tx = tid & 31, ty = tid >> 5;
    float4 fbv = ((const float4*)fb)[tx];
    float4 acc[8];
#pragma unroll
    for (int i = 0; i < 8; i++) acc[i] = fbv;

    // W = f2 @ fw + fb  (K = 64)
#pragma unroll 4
    for (int g4 = 0; g4 < GG / 4; g4++) {
        float4 b0 = *(const float4*)&s_fw[(4 * g4 + 0) * DD + tx * 4];
        float4 b1 = *(const float4*)&s_fw[(4 * g4 + 1) * DD + tx * 4];
        float4 b2 = *(const float4*)&s_fw[(4 * g4 + 2) * DD + tx * 4];
        float4 b3 = *(const float4*)&s_fw[(4 * g4 + 3) * DD + tx * 4];
#pragma unroll
        for (int i = 0; i < 8; i++) {
            float4 a = *(const float4*)&s_f2[(ty * 8 + i) * GG + 4 * g4];
            acc[i].x += a.x * b0.x + a.y * b1.x + a.z * b2.x + a.w * b3.x;
            acc[i].y += a.x * b0.y + a.y * b1.y + a.z * b2.y + a.w * b3.y;
            acc[i].z += a.x * b0.z + a.y * b1.z + a.z * b2.z + a.w * b3.z;
            acc[i].w += a.x * b0.w + a.y * b1.w + a.z * b2.w + a.w * b3.w;
        }
    }

    float4 gv = ((const float4*)lng)[tx];
    float4 bv = ((const float4*)lnb)[tx];
#pragma unroll
    for (int i = 0; i < 8; i++) {
        int el = ty * 8 + i;
        int e = base + el;
        float C = s_C[el];
        float4 w = acc[i];
        w.x *= C; w.y *= C; w.z *= C; w.w *= C;
        ((float4*)outW)[(size_t)e * 32 + tx] = w;  // output W

        int dI = s_dst[el];
        float4 hv = ((const float4*)h1)[(size_t)dI * 32 + tx];
        float4 tv = ((const float4*)t_in)[(size_t)e * 32 + tx];
        float4 q;
        q.x = w.x * hv.x + tv.x;
        q.y = w.y * hv.y + tv.y;
        q.z = w.z * hv.z + tv.z;
        q.w = w.w * hv.w + tv.w;

        // LayerNorm across D=128 (row spread across 32 lanes x 4)
        float ps = q.x + q.y + q.z + q.w;
        float pss = q.x * q.x + q.y * q.y + q.z * q.z + q.w * q.w;
#pragma unroll
        for (int o = 16; o; o >>= 1) {
            ps += __shfl_xor_sync(0xffffffffu, ps, o);
            pss += __shfl_xor_sync(0xffffffffu, pss, o);
        }
        float mu = ps * (1.0f / 128.0f);
        float var = pss * (1.0f / 128.0f) - mu * mu;
        float rstd = rsqrtf(var + LN_EPS);
        q.x = (q.x - mu) * rstd * gv.x + bv.x;
        q.y = (q.y - mu) * rstd * gv.y + bv.y;
        q.z = (q.z - mu) * rstd * gv.z + bv.z;
        q.w = (q.w - mu) * rstd * gv.w + bv.w;
        ((float4*)g_q)[(size_t)e * 32 + tx] = q;
    }
}

// shared GEMM inner: out[64 rows x 128] = s_A[64x128] @ s_B[128x128]
__device__ __forceinline__ void gemm_tile(const float* s_A, const float* s_B,
                                          float4 acc[8], int tx, int ty)
{
#pragma unroll 4
    for (int k4 = 0; k4 < DD / 4; k4++) {
        float4 b0 = *(const float4*)&s_B[(4 * k4 + 0) * DD + tx * 4];
        float4 b1 = *(const float4*)&s_B[(4 * k4 + 1) * DD + tx * 4];
        float4 b2 = *(const float4*)&s_B[(4 * k4 + 2) * DD + tx * 4];
        float4 b3 = *(const float4*)&s_B[(4 * k4 + 3) * DD + tx * 4];
#pragma unroll
        for (int i = 0; i < 8; i++) {
            float4 a = *(const float4*)&s_A[(ty * 8 + i) * DD + 4 * k4];
            acc[i].x += a.x * b0.x + a.y * b1.x + a.z * b2.x + a.w * b3.x;
            acc[i].y += a.x * b0.y + a.y * b1.y + a.z * b2.y + a.w * b3.y;
            acc[i].z += a.x * b0.z + a.y * b1.z + a.z * b2.z + a.w * b3.z;
            acc[i].w += a.x * b0.w + a.y * b1.w + a.z * b2.w + a.w * b3.w;
        }
    }
}

// ---------------- K2: q_vec = q[q_id] @ Wq  (node-level) -------------------
__global__ __launch_bounds__(256) void k_qvec(const float* __restrict__ Wq,
                                              const int* __restrict__ q_id)
{
    extern __shared__ float sm[];
    float* s_A = sm;            // 64 x 128
    float* s_B = sm + 64 * DD;  // 128 x 128
    const int tid = threadIdx.x;
    const int base = blockIdx.x * 64;

    for (int i = tid; i < DD * DD / 4; i += 256)
        ((float4*)s_B)[i] = ((const float4*)Wq)[i];
    for (int i = tid; i < 64 * DD / 4; i += 256) {
        int row = i >> 5, c4 = i & 31;
        int gr = base + row;
        float4 vv = make_float4(0.f, 0.f, 0.f, 0.f);
        if (gr < NN) {
            int ar = q_id[gr];
            vv = ((const float4*)g_q)[(size_t)ar * 32 + c4];
        }
        ((float4*)s_A)[i] = vv;
    }
    __syncthreads();

    const int tx = tid & 31, ty = tid >> 5;
    float4 acc[8];
#pragma unroll
    for (int i = 0; i < 8; i++) acc[i] = make_float4(0.f, 0.f, 0.f, 0.f);
    gemm_tile(s_A, s_B, acc, tx, ty);
#pragma unroll
    for (int i = 0; i < 8; i++) {
        int gr = base + ty * 8 + i;
        if (gr < NN) ((float4*)g_qvec)[(size_t)gr * 32 + tx] = acc[i];
    }
}

// ---------------- K3: k = q@Wk -> logits (in-register), v = q@Wv -> g_v ----
__global__ __launch_bounds__(256) void k_kv(const float* __restrict__ Wk,
                                            const float* __restrict__ Wv,
                                            const int* __restrict__ src)
{
    extern __shared__ float sm[];
    float* s_A = sm;            // 64 x 128 (q tile)
    float* s_B = sm + 64 * DD;  // 128 x 128 (Wk then Wv)
    __shared__ int s_src[64];
    const int tid = threadIdx.x;
    const int base = blockIdx.x * 64;

    for (int i = tid; i < 64 * DD / 4; i += 256) {
        int row = i >> 5, c4 = i & 31;
        ((float4*)s_A)[i] = ((const float4*)g_q)[(size_t)(base + row) * 32 + c4];
    }
    if (tid < 64) s_src[tid] = src[base + tid];
    for (int i = tid; i < DD * DD / 4; i += 256)
        ((float4*)s_B)[i] = ((const float4*)Wk)[i];
    __syncthreads();

    const int tx = tid & 31, ty = tid >> 5;
    float4 acc[8];
#pragma unroll
    for (int i = 0; i < 8; i++) acc[i] = make_float4(0.f, 0.f, 0.f, 0.f);
    gemm_tile(s_A, s_B, acc, tx, ty);

    // logits: per-head dot(q_vec[src], k) ; head h owns lanes 4h..4h+3
    const int h = tx >> 2;
#pragma unroll
    for (int i = 0; i < 8; i++) {
        int el = ty * 8 + i;
        int e = base + el;
        int sI = s_src[el];
        float4 qv = ((const float4*)g_qvec)[(size_t)sI * 32 + tx];
        float part = acc[i].x * qv.x + acc[i].y * qv.y + acc[i].z * qv.z + acc[i].w * qv.w;
        part += __shfl_xor_sync(0xffffffffu, part, 1);
        part += __shfl_xor_sync(0xffffffffu, part, 2);
        float logit = part * 0.25f; // 1/sqrt(P=16)
        if ((tx & 3) == 0) {
            g_logit[(size_t)e * HH + h] = logit;
            atomicMax(&g_mmax[(size_t)sI * HH + h], fenc(logit));
        }
    }
    __syncthreads();

    for (int i = tid; i < DD * DD / 4; i += 256)
        ((float4*)s_B)[i] = ((const float4*)Wv)[i];
    __syncthreads();

#pragma unroll
    for (int i = 0; i < 8; i++) acc[i] = make_float4(0.f, 0.f, 0.f, 0.f);
    gemm_tile(s_A, s_B, acc, tx, ty);
#pragma unroll
    for (int i = 0; i < 8; i++) {
        int e = base + ty * 8 + i;
        ((float4*)g_v)[(size_t)e * 32 + tx] = acc[i];
    }
}

// ---------------- K4: a = exp(logit - m[src]) * C ; segment-sum ------------
// (softmax z cancels exactly against post-cutoff renorm: att = aC / sum(aC))
__global__ void k_soft(const int* __restrict__ src) {
    int t = blockIdx.x * blockDim.x + threadIdx.x;
    if (t >= EE * HH) return;
    int e = t >> 3, h = t & 7;
    int sI = src[e];
    float m = fdec(g_mmax[(size_t)sI * HH + h]);
    float a = __expf(g_logit[t] - m) * g_C[e];
    g_logit[t] = a;
    atomicAdd(&g_ssum[(size_t)sI * HH + h], a);
}

// ---------------- K5: he = v * att ; scatter-add to h2[src] ----------------
__global__ __launch_bounds__(256) void k_scatter(const int* __restrict__ src) {
    const int tid = threadIdx.x;
    const int tx = tid & 31, wid = tid >> 5;
    int e = blockIdx.x * 8 + wid;
    int sI = __ldg(&src[e]);
    int h = tx >> 2;
    float att = g_logit[(size_t)e * HH + h] / g_ssum[(size_t)sI * HH + h];
    float4 v = ((const float4*)g_v)[(size_t)e * 32 + tx];
    float* dp = &g_h2[(size_t)sI * DD + tx * 4];
    atomicAdd(dp + 0, v.x * att);
    atomicAdd(dp + 1, v.y * att);
    atomicAdd(dp + 2, v.z * att);
    atomicAdd(dp + 3, v.w * att);
}

// ---------------- K6: m_agg = h2 @ Wo --------------------------------------
__global__ __launch_bounds__(256) void k_out(const float* __restrict__ Wo,
                                             float* __restrict__ outM)
{
    extern __shared__ float sm[];
    float* s_A = sm;
    float* s_B = sm + 64 * DD;
    const int tid = threadIdx.x;
    const int base = blockIdx.x * 64;

    for (int i = tid; i < DD * DD / 4; i += 256)
        ((float4*)s_B)[i] = ((const float4*)Wo)[i];
    for (int i = tid; i < 64 * DD / 4; i += 256) {
        int row = i >> 5, c4 = i & 31;
        int gr = base + row;
        float4 vv = make_float4(0.f, 0.f, 0.f, 0.f);
        if (gr < NN) vv = ((const float4*)g_h2)[(size_t)gr * 32 + c4];
        ((float4*)s_A)[i] = vv;
    }
    __syncthreads();

    const int tx = tid & 31, ty = tid >> 5;
    float4 acc[8];
#pragma unroll
    for (int i = 0; i < 8; i++) acc[i] = make_float4(0.f, 0.f, 0.f, 0.f);
    gemm_tile(s_A, s_B, acc, tx, ty);
#pragma unroll
    for (int i = 0; i < 8; i++) {
        int gr = base + ty * 8 + i;
        if (gr < NN) ((float4*)outM)[(size_t)gr * 32 + tx] = acc[i];
    }
}

// ---------------------------------------------------------------------------
extern "C" void kernel_launch(void* const* d_in, const int* in_sizes, int n_in,
                              void* d_out, int out_size)
{
    const float* pos  = (const float*)d_in[0];
    const float* h1   = (const float*)d_in[1];
    const float* t_in = (const float*)d_in[2];
    const float* fw   = (const float*)d_in[3];
    const float* fb   = (const float*)d_in[4];
    const float* lng  = (const float*)d_in[5];
    const float* lnb  = (const float*)d_in[6];
    const float* Wq   = (const float*)d_in[7];
    const float* Wk   = (const float*)d_in[8];
    const float* Wv   = (const float*)d_in[9];
    const float* Wo   = (const float*)d_in[10];
    const int* src    = (const int*)d_in[11];
    const int* dst    = (const int*)d_in[12];
    const int* q_id   = (const int*)d_in[13];

    float* outM = (float*)d_out;                       // [N, D]
    float* outW = outM + (size_t)NN * DD;              // [E, D]

    const int smem_filter = (GG * DD + 64 * GG) * sizeof(float);        // 48KB
    const int smem_gemm   = (64 * DD + DD * DD) * sizeof(float);        // 96KB
    cudaFuncSetAttribute(k_edge_filter, cudaFuncAttributeMaxDynamicSharedMemorySize, smem_filter);
    cudaFuncSetAttribute(k_qvec, cudaFuncAttributeMaxDynamicSharedMemorySize, smem_gemm);
    cudaFuncSetAttribute(k_kv,   cudaFuncAttributeMaxDynamicSharedMemorySize, smem_gemm);
    cudaFuncSetAttribute(k_out,  cudaFuncAttributeMaxDynamicSharedMemorySize, smem_gemm);

    k_init<<<(NN * DD + 255) / 256, 256>>>();
    k_edge_filter<<<EE / 64, 256, smem_filter>>>(pos, h1, t_in, fw, fb, lng, lnb,
                                                 src, dst, outW);
    k_qvec<<<(NN + 63) / 64, 256, smem_gemm>>>(Wq, q_id);
    k_kv<<<EE / 64, 256, smem_gemm>>>(Wk, Wv, src);
    k_soft<<<(EE * HH + 255) / 256, 256>>>(src);
    k_scatter<<<EE / 8, 256>>>(src);
    k_out<<<(NN + 63) / 64, 256, smem_gemm>>>(Wo, outM);
}

// round 2
// speedup vs baseline: 1.2243x; 1.2243x over previous
#include <cuda_runtime.h>
#include <math.h>

#define NN 20000
#define EE 320000
#define DD 128
#define HH 8
#define PP 16
#define GG 64
#define WIDTHF (5.0f/63.0f)
#define LN_EPS 1e-5f

// ---------------- scratch (device globals; no allocation allowed) ----------
__device__ float g_q[(size_t)EE*DD];      // layernormed edge features
__device__ float g_v[(size_t)EE*DD];      // v_vec
__device__ float g_logit[(size_t)EE*HH];  // logits, then exp-numerators
__device__ float g_C[EE];                 // cosine cutoff per edge
__device__ float g_qvec[(size_t)NN*DD];   // node-level q
__device__ float g_h2[(size_t)NN*DD];     // aggregated he
__device__ int   g_mmax[(size_t)NN*HH];   // segment max (monotone-int encoded)
__device__ float g_ssum[(size_t)NN*HH];   // segment sum of a*C

// monotone float<->int encoding for atomicMax on signed int
__device__ __forceinline__ int fenc(float f) {
    int i = __float_as_int(f);
    return (i < 0) ? (i ^ 0x7fffffff) : i;
}
__device__ __forceinline__ float fdec(int i) {
    return __int_as_float((i < 0) ? (i ^ 0x7fffffff) : i);
}

__device__ __forceinline__ float tf32r(float x) {
    unsigned int o;
    asm("cvt.rna.tf32.f32 %0, %1;" : "=r"(o) : "f"(x));
    return __uint_as_float(o);
}

// ---------------- init segment buffers ------------------------------------
__global__ void k_init() {
    int t = blockIdx.x * blockDim.x + threadIdx.x;
    if (t < NN * DD) g_h2[t] = 0.0f;
    if (t < NN * HH) {
        g_mmax[t] = fenc(__int_as_float(0xff800000)); // -inf
        g_ssum[t] = 0.0f;
    }
}

// ---------------- K1: distances, RBF filter GEMM, cutoff, q = LN(W*h1[dst]+t)
__global__ __launch_bounds__(256) void k_edge_filter(
    const float* __restrict__ pos, const float* __restrict__ h1,
    const float* __restrict__ t_in, const float* __restrict__ fw,
    const float* __restrict__ fb, const float* __restrict__ lng,
    const float* __restrict__ lnb, const int* __restrict__ src,
    const int* __restrict__ dst, float* __restrict__ outW)
{
    extern __shared__ float sm[];
    float* s_fw = sm;                 // [GG][DD] 32KB
    float* s_f2 = sm + GG * DD;       // [64][GG] 16KB
    __shared__ float s_r[64], s_C[64];
    __shared__ int s_dst[64];

    const int tid = threadIdx.x;
    const int base = blockIdx.x * 64;

    for (int i = tid; i < GG * DD / 4; i += 256)
        ((float4*)s_fw)[i] = ((const float4*)fw)[i];

    if (tid < 64) {
        int e = base + tid;
        int sI = src[e], dI = dst[e];
        float dx = pos[dI * 3 + 0] - pos[sI * 3 + 0];
        float dy = pos[dI * 3 + 1] - pos[sI * 3 + 1];
        float dz = pos[dI * 3 + 2] - pos[sI * 3 + 2];
        float r = sqrtf(dx * dx + dy * dy + dz * dz);
        float C = (r < 5.0f) ? 0.5f * (cospif(r * 0.2f) + 1.0f) : 0.0f;
        s_r[tid] = r; s_C[tid] = C; s_dst[tid] = dI;
        g_C[e] = C;
    }
    __syncthreads();

    const float alpha = -0.5f / (WIDTHF * WIDTHF);
    for (int idx = tid; idx < 64 * GG; idx += 256) {
        int e = idx >> 6, g = idx & 63;
        float diff = s_r[e] - (float)g * WIDTHF;
        float f2 = (fabsf(diff) < 8.0f * WIDTHF)
                       ? 2.0f * __expf(alpha * diff * diff) - 1.0f
                       : -1.0f;
        s_f2[e * GG + g] = f2;
    }
    __syncthreads();

    const int tx = tid & 31, ty = tid >> 5;
    float4 fbv = ((const float4*)fb)[tx];
    float4 acc[8];
#pragma unroll
    for (int i = 0; i < 8; i++) acc[i] = fbv;

#pragma unroll 4
    for (int g4 = 0; g4 < GG / 4; g4++) {
        float4 b0 = *(const float4*)&s_fw[(4 * g4 + 0) * DD + tx * 4];
        float4 b1 = *(const float4*)&s_fw[(4 * g4 + 1) * DD + tx * 4];
        float4 b2 = *(const float4*)&s_fw[(4 * g4 + 2) * DD + tx * 4];
        float4 b3 = *(const float4*)&s_fw[(4 * g4 + 3) * DD + tx * 4];
#pragma unroll
        for (int i = 0; i < 8; i++) {
            float4 a = *(const float4*)&s_f2[(ty * 8 + i) * GG + 4 * g4];
            acc[i].x += a.x * b0.x + a.y * b1.x + a.z * b2.x + a.w * b3.x;
            acc[i].y += a.x * b0.y + a.y * b1.y + a.z * b2.y + a.w * b3.y;
            acc[i].z += a.x * b0.z + a.y * b1.z + a.z * b2.z + a.w * b3.z;
            acc[i].w += a.x * b0.w + a.y * b1.w + a.z * b2.w + a.w * b3.w;
        }
    }

    float4 gv = ((const float4*)lng)[tx];
    float4 bv = ((const float4*)lnb)[tx];
#pragma unroll
    for (int i = 0; i < 8; i++) {
        int el = ty * 8 + i;
        int e = base + el;
        float C = s_C[el];
        float4 w = acc[i];
        w.x *= C; w.y *= C; w.z *= C; w.w *= C;
        ((float4*)outW)[(size_t)e * 32 + tx] = w;

        int dI = s_dst[el];
        float4 hv = ((const float4*)h1)[(size_t)dI * 32 + tx];
        float4 tv = ((const float4*)t_in)[(size_t)e * 32 + tx];
        float4 q;
        q.x = w.x * hv.x + tv.x;
        q.y = w.y * hv.y + tv.y;
        q.z = w.z * hv.z + tv.z;
        q.w = w.w * hv.w + tv.w;

        float ps = q.x + q.y + q.z + q.w;
        float pss = q.x * q.x + q.y * q.y + q.z * q.z + q.w * q.w;
#pragma unroll
        for (int o = 16; o; o >>= 1) {
            ps += __shfl_xor_sync(0xffffffffu, ps, o);
            pss += __shfl_xor_sync(0xffffffffu, pss, o);
        }
        float mu = ps * (1.0f / 128.0f);
        float var = pss * (1.0f / 128.0f) - mu * mu;
        float rstd = rsqrtf(var + LN_EPS);
        q.x = (q.x - mu) * rstd * gv.x + bv.x;
        q.y = (q.y - mu) * rstd * gv.y + bv.y;
        q.z = (q.z - mu) * rstd * gv.z + bv.z;
        q.w = (q.w - mu) * rstd * gv.w + bv.w;
        ((float4*)g_q)[(size_t)e * 32 + tx] = q;
    }
}

// SIMT GEMM inner: out[64 rows x 128] = s_A[64x128] @ s_B[128x128]
__device__ __forceinline__ void gemm_tile(const float* s_A, const float* s_B,
                                          float4 acc[8], int tx, int ty)
{
#pragma unroll 4
    for (int k4 = 0; k4 < DD / 4; k4++) {
        float4 b0 = *(const float4*)&s_B[(4 * k4 + 0) * DD + tx * 4];
        float4 b1 = *(const float4*)&s_B[(4 * k4 + 1) * DD + tx * 4];
        float4 b2 = *(const float4*)&s_B[(4 * k4 + 2) * DD + tx * 4];
        float4 b3 = *(const float4*)&s_B[(4 * k4 + 3) * DD + tx * 4];
#pragma unroll
        for (int i = 0; i < 8; i++) {
            float4 a = *(const float4*)&s_A[(ty * 8 + i) * DD + 4 * k4];
            acc[i].x += a.x * b0.x + a.y * b1.x + a.z * b2.x + a.w * b3.x;
            acc[i].y += a.x * b0.y + a.y * b1.y + a.z * b2.y + a.w * b3.y;
            acc[i].z += a.x * b0.z + a.y * b1.z + a.z * b2.z + a.w * b3.z;
            acc[i].w += a.x * b0.w + a.y * b1.w + a.z * b2.w + a.w * b3.w;
        }
    }
}

// ---------------- K2: q_vec = q[q_id] @ Wq  (node-level) -------------------
__global__ __launch_bounds__(256) void k_qvec(const float* __restrict__ Wq,
                                              const int* __restrict__ q_id)
{
    extern __shared__ float sm[];
    float* s_A = sm;
    float* s_B = sm + 64 * DD;
    const int tid = threadIdx.x;
    const int base = blockIdx.x * 64;

    for (int i = tid; i < DD * DD / 4; i += 256)
        ((float4*)s_B)[i] = ((const float4*)Wq)[i];
    for (int i = tid; i < 64 * DD / 4; i += 256) {
        int row = i >> 5, c4 = i & 31;
        int gr = base + row;
        float4 vv = make_float4(0.f, 0.f, 0.f, 0.f);
        if (gr < NN) {
            int ar = q_id[gr];
            vv = ((const float4*)g_q)[(size_t)ar * 32 + c4];
        }
        ((float4*)s_A)[i] = vv;
    }
    __syncthreads();

    const int tx = tid & 31, ty = tid >> 5;
    float4 acc[8];
#pragma unroll
    for (int i = 0; i < 8; i++) acc[i] = make_float4(0.f, 0.f, 0.f, 0.f);
    gemm_tile(s_A, s_B, acc, tx, ty);
#pragma unroll
    for (int i = 0; i < 8; i++) {
        int gr = base + ty * 8 + i;
        if (gr < NN) ((float4*)g_qvec)[(size_t)gr * 32 + tx] = acc[i];
    }
}

// ---------------- K3 (tensor): k = q@Wk -> logits ; v = q@Wv -> g_v --------
// Block: 256 threads (8 warps, 4x2), tile M=128 edges, N=128, K=128.
// mma.sync.m16n8k8 tf32; k never materialized.
#define QPAD 132   // A-tile stride (conflict-free A fragment loads)
#define BPAD 136   // B-tile stride (conflict-free B fragment loads)

__device__ __forceinline__ void mma_tf32(float c[4], const unsigned a[4],
                                         const unsigned b[2])
{
    asm volatile(
        "mma.sync.aligned.m16n8k8.row.col.f32.tf32.tf32.f32 "
        "{%0,%1,%2,%3}, {%4,%5,%6,%7}, {%8,%9}, {%0,%1,%2,%3};"
        : "+f"(c[0]), "+f"(c[1]), "+f"(c[2]), "+f"(c[3])
        : "r"(a[0]), "r"(a[1]), "r"(a[2]), "r"(a[3]), "r"(b[0]), "r"(b[1]));
}

__global__ __launch_bounds__(256) void k_kv(const float* __restrict__ Wk,
                                            const float* __restrict__ Wv,
                                            const int* __restrict__ src)
{
    extern __shared__ float sm[];
    float* s_q = sm;               // [128][QPAD]
    float* s_B = sm + 128 * QPAD;  // [128][BPAD]
    __shared__ int s_src[128];

    const int tid = threadIdx.x;
    const int lane = tid & 31;
    const int wid = tid >> 5;
    const int warpM = wid & 3;       // 4 warps along M (32 rows each)
    const int warpN = wid >> 2;      // 2 warps along N (64 cols each)
    const int base = blockIdx.x * 128;

    // stage q tile (tf32-rounded) + src
    for (int i = tid; i < 128 * 32; i += 256) {
        int row = i >> 5, c4 = i & 31;
        float4 v = ((const float4*)g_q)[(size_t)(base + row) * 32 + c4];
        v.x = tf32r(v.x); v.y = tf32r(v.y); v.z = tf32r(v.z); v.w = tf32r(v.w);
        *(float4*)&s_q[row * QPAD + c4 * 4] = v;
    }
    if (tid < 128) s_src[tid] = src[base + tid];
    // stage Wk (tf32-rounded); B[k][n] = Wk[k][n] directly (row.col mma)
    for (int i = tid; i < 128 * 32; i += 256) {
        int row = i >> 5, c4 = i & 31;
        float4 v = ((const float4*)Wk)[i];
        v.x = tf32r(v.x); v.y = tf32r(v.y); v.z = tf32r(v.z); v.w = tf32r(v.w);
        *(float4*)&s_B[row * BPAD + c4 * 4] = v;
    }
    __syncthreads();

    const int rA = warpM * 32 + (lane >> 2);   // A fragment base row
    const int cN = warpN * 64 + (lane >> 2);   // B fragment base col
    const int kA = lane & 3;

    float c[2][8][4];
#pragma unroll
    for (int mt = 0; mt < 2; mt++)
#pragma unroll
        for (int nt = 0; nt < 8; nt++)
#pragma unroll
            for (int j = 0; j < 4; j++) c[mt][nt][j] = 0.0f;

    // ---- pass 1: k = q @ Wk (in fragments) ----
#pragma unroll 2
    for (int ks = 0; ks < 16; ks++) {
        int k0 = ks * 8;
        unsigned a[2][4], b[8][2];
#pragma unroll
        for (int mt = 0; mt < 2; mt++) {
            const float* ap = &s_q[(rA + mt * 16) * QPAD + k0 + kA];
            a[mt][0] = __float_as_uint(ap[0]);
            a[mt][1] = __float_as_uint(ap[8 * QPAD]);
            a[mt][2] = __float_as_uint(ap[4]);
            a[mt][3] = __float_as_uint(ap[8 * QPAD + 4]);
        }
#pragma unroll
        for (int nt = 0; nt < 8; nt++) {
            const float* bp = &s_B[(k0 + kA) * BPAD + cN + nt * 8];
            b[nt][0] = __float_as_uint(bp[0]);
            b[nt][1] = __float_as_uint(bp[4 * BPAD]);
        }
#pragma unroll
        for (int mt = 0; mt < 2; mt++)
#pragma unroll
            for (int nt = 0; nt < 8; nt++)
                mma_tf32(c[mt][nt], a[mt], b[nt]);
    }

    // ---- epilogue 1: logits via per-head dot with q_vec[src] ----
    {
        float ph[2][2][4];   // [mt][rowhalf][local head]
#pragma unroll
        for (int mt = 0; mt < 2; mt++)
#pragma unroll
            for (int hf = 0; hf < 2; hf++)
#pragma unroll
                for (int h = 0; h < 4; h++) ph[mt][hf][h] = 0.0f;

        const int col0base = warpN * 64 + 2 * (lane & 3);
#pragma unroll
        for (int mt = 0; mt < 2; mt++) {
#pragma unroll
            for (int hf = 0; hf < 2; hf++) {
                int r = rA + mt * 16 + hf * 8;
                int sI = s_src[r];
                const float* qv = &g_qvec[(size_t)sI * DD];
#pragma unroll
                for (int nt = 0; nt < 8; nt++) {
                    float2 q2 = *(const float2*)&qv[col0base + nt * 8];
                    ph[mt][hf][nt >> 1] +=
                        c[mt][nt][2 * hf] * q2.x + c[mt][nt][2 * hf + 1] * q2.y;
                }
            }
        }
#pragma unroll
        for (int mt = 0; mt < 2; mt++)
#pragma unroll
            for (int hf = 0; hf < 2; hf++)
#pragma unroll
                for (int h = 0; h < 4; h++) {
                    float v = ph[mt][hf][h];
                    v += __shfl_xor_sync(0xffffffffu, v, 1);
                    v += __shfl_xor_sync(0xffffffffu, v, 2);
                    ph[mt][hf][h] = v;
                }
        // lane (lane&3) writes local head (lane&3)
        int hl = lane & 3;
        int head = warpN * 4 + hl;
#pragma unroll
        for (int mt = 0; mt < 2; mt++)
#pragma unroll
            for (int hf = 0; hf < 2; hf++) {
                int r = rA + mt * 16 + hf * 8;
                int e = base + r;
                int sI = s_src[r];
                float logit = ph[mt][hf][hl] * 0.25f;  // 1/sqrt(P=16)
                g_logit[(size_t)e * HH + head] = logit;
                atomicMax(&g_mmax[(size_t)sI * HH + head], fenc(logit));
            }
    }

    __syncthreads();  // pass-1 B reads done everywhere

    // stage Wv
    for (int i = tid; i < 128 * 32; i += 256) {
        int row = i >> 5, c4 = i & 31;
        float4 v = ((const float4*)Wv)[i];
        v.x = tf32r(v.x); v.y = tf32r(v.y); v.z = tf32r(v.z); v.w = tf32r(v.w);
        *(float4*)&s_B[row * BPAD + c4 * 4] = v;
    }
    __syncthreads();

#pragma unroll
    for (int mt = 0; mt < 2; mt++)
#pragma unroll
        for (int nt = 0; nt < 8; nt++)
#pragma unroll
            for (int j = 0; j < 4; j++) c[mt][nt][j] = 0.0f;

    // ---- pass 2: v = q @ Wv ----
#pragma unroll 2
    for (int ks = 0; ks < 16; ks++) {
        int k0 = ks * 8;
        unsigned a[2][4], b[8][2];
#pragma unroll
        for (int mt = 0; mt < 2; mt++) {
            const float* ap = &s_q[(rA + mt * 16) * QPAD + k0 + kA];
            a[mt][0] = __float_as_uint(ap[0]);
            a[mt][1] = __float_as_uint(ap[8 * QPAD]);
            a[mt][2] = __float_as_uint(ap[4]);
            a[mt][3] = __float_as_uint(ap[8 * QPAD + 4]);
        }
#pragma unroll
        for (int nt = 0; nt < 8; nt++) {
            const float* bp = &s_B[(k0 + kA) * BPAD + cN + nt * 8];
            b[nt][0] = __float_as_uint(bp[0]);
            b[nt][1] = __float_as_uint(bp[4 * BPAD]);
        }
#pragma unroll
        for (int mt = 0; mt < 2; mt++)
#pragma unroll
            for (int nt = 0; nt < 8; nt++)
                mma_tf32(c[mt][nt], a[mt], b[nt]);
    }

    // ---- epilogue 2: store v fragments ----
    const int col0 = warpN * 64 + 2 * (lane & 3);
#pragma unroll
    for (int mt = 0; mt < 2; mt++) {
        int r = rA + mt * 16;
#pragma unroll
        for (int nt = 0; nt < 8; nt++) {
            int cc = col0 + nt * 8;
            *(float2*)&g_v[(size_t)(base + r) * DD + cc] =
                make_float2(c[mt][nt][0], c[mt][nt][1]);
            *(float2*)&g_v[(size_t)(base + r + 8) * DD + cc] =
                make_float2(c[mt][nt][2], c[mt][nt][3]);
        }
    }
}

// ---------------- K4: a = exp(logit - m[src]) * C ; segment-sum ------------
__global__ void k_soft(const int* __restrict__ src) {
    int t = blockIdx.x * blockDim.x + threadIdx.x;
    if (t >= EE * HH) return;
    int e = t >> 3, h = t & 7;
    int sI = src[e];
    float m = fdec(g_mmax[(size_t)sI * HH + h]);
    float a = __expf(g_logit[t] - m) * g_C[e];
    g_logit[t] = a;
    atomicAdd(&g_ssum[(size_t)sI * HH + h], a);
}

// ---------------- K5: he = v * att ; scatter-add to h2[src] ----------------
__global__ __launch_bounds__(256) void k_scatter(const int* __restrict__ src) {
    const int tid = threadIdx.x;
    const int tx = tid & 31, wid = tid >> 5;
    int e = blockIdx.x * 8 + wid;
    int sI = __ldg(&src[e]);
    int h = tx >> 2;
    float att = g_logit[(size_t)e * HH + h] / g_ssum[(size_t)sI * HH + h];
    float4 v = ((const float4*)g_v)[(size_t)e * 32 + tx];
    float* dp = &g_h2[(size_t)sI * DD + tx * 4];
    atomicAdd(dp + 0, v.x * att);
    atomicAdd(dp + 1, v.y * att);
    atomicAdd(dp + 2, v.z * att);
    atomicAdd(dp + 3, v.w * att);
}

// ---------------- K6: m_agg = h2 @ Wo --------------------------------------
__global__ __launch_bounds__(256) void k_out(const float* __restrict__ Wo,
                                             float* __restrict__ outM)
{
    extern __shared__ float sm[];
    float* s_A = sm;
    float* s_B = sm + 64 * DD;
    const int tid = threadIdx.x;
    const int base = blockIdx.x * 64;

    for (int i = tid; i < DD * DD / 4; i += 256)
        ((float4*)s_B)[i] = ((const float4*)Wo)[i];
    for (int i = tid; i < 64 * DD / 4; i += 256) {
        int row = i >> 5, c4 = i & 31;
        int gr = base + row;
        float4 vv = make_float4(0.f, 0.f, 0.f, 0.f);
        if (gr < NN) vv = ((const float4*)g_h2)[(size_t)gr * 32 + c4];
        ((float4*)s_A)[i] = vv;
    }
    __syncthreads();

    const int tx = tid & 31, ty = tid >> 5;
    float4 acc[8];
#pragma unroll
    for (int i = 0; i < 8; i++) acc[i] = make_float4(0.f, 0.f, 0.f, 0.f);
    gemm_tile(s_A, s_B, acc, tx, ty);
#pragma unroll
    for (int i = 0; i < 8; i++) {
        int gr = base + ty * 8 + i;
        if (gr < NN) ((float4*)outM)[(size_t)gr * 32 + tx] = acc[i];
    }
}

// ---------------------------------------------------------------------------
extern "C" void kernel_launch(void* const* d_in, const int* in_sizes, int n_in,
                              void* d_out, int out_size)
{
    const float* pos  = (const float*)d_in[0];
    const float* h1   = (const float*)d_in[1];
    const float* t_in = (const float*)d_in[2];
    const float* fw   = (const float*)d_in[3];
    const float* fb   = (const float*)d_in[4];
    const float* lng  = (const float*)d_in[5];
    const float* lnb  = (const float*)d_in[6];
    const float* Wq   = (const float*)d_in[7];
    const float* Wk   = (const float*)d_in[8];
    const float* Wv   = (const float*)d_in[9];
    const float* Wo   = (const float*)d_in[10];
    const int* src    = (const int*)d_in[11];
    const int* dst    = (const int*)d_in[12];
    const int* q_id   = (const int*)d_in[13];

    float* outM = (float*)d_out;                       // [N, D]
    float* outW = outM + (size_t)NN * DD;              // [E, D]

    const int smem_filter = (GG * DD + 64 * GG) * sizeof(float);       // 48KB
    const int smem_gemm   = (64 * DD + DD * DD) * sizeof(float);       // 96KB
    const int smem_kv     = (128 * QPAD + 128 * BPAD) * sizeof(float); // ~134KB
    cudaFuncSetAttribute(k_edge_filter, cudaFuncAttributeMaxDynamicSharedMemorySize, smem_filter);
    cudaFuncSetAttribute(k_qvec, cudaFuncAttributeMaxDynamicSharedMemorySize, smem_gemm);
    cudaFuncSetAttribute(k_kv,   cudaFuncAttributeMaxDynamicSharedMemorySize, smem_kv);
    cudaFuncSetAttribute(k_out,  cudaFuncAttributeMaxDynamicSharedMemorySize, smem_gemm);

    k_init<<<(NN * DD + 255) / 256, 256>>>();
    k_edge_filter<<<EE / 64, 256, smem_filter>>>(pos, h1, t_in, fw, fb, lng, lnb,
                                                 src, dst, outW);
    k_qvec<<<(NN + 63) / 64, 256, smem_gemm>>>(Wq, q_id);
    k_kv<<<EE / 128, 256, smem_kv>>>(Wk, Wv, src);
    k_soft<<<(EE * HH + 255) / 256, 256>>>(src);
    k_scatter<<<EE / 8, 256>>>(src);
    k_out<<<(NN + 63) / 64, 256, smem_gemm>>>(Wo, outM);
}

// round 3
// speedup vs baseline: 1.4603x; 1.1928x over previous
#include <cuda_runtime.h>
#include <math.h>

#define NN 20000
#define EE 320000
#define DD 128
#define HH 8
#define PP 16
#define GG 64
#define WIDTHF (5.0f/63.0f)
#define LN_EPS 1e-5f

// ---------------- scratch (device globals; no allocation allowed) ----------
__device__ float g_q[(size_t)EE*DD];      // layernormed edge features
__device__ float g_v[(size_t)EE*DD];      // v_vec
__device__ float g_logit[(size_t)EE*HH];  // logits, then exp-numerators
__device__ float g_C[EE];                 // cosine cutoff per edge
__device__ float g_qvec[(size_t)NN*DD];   // node-level q
__device__ float g_h2[(size_t)NN*DD];     // aggregated he
__device__ int   g_mmax[(size_t)NN*HH];   // segment max (monotone-int encoded)
__device__ float g_ssum[(size_t)NN*HH];   // segment sum of a*C

// monotone float<->int encoding for atomicMax on signed int
__device__ __forceinline__ int fenc(float f) {
    int i = __float_as_int(f);
    return (i < 0) ? (i ^ 0x7fffffff) : i;
}
__device__ __forceinline__ float fdec(int i) {
    return __int_as_float((i < 0) ? (i ^ 0x7fffffff) : i);
}

__device__ __forceinline__ float tf32r(float x) {
    unsigned int o;
    asm("cvt.rna.tf32.f32 %0, %1;" : "=r"(o) : "f"(x));
    return __uint_as_float(o);
}

// ---------------- init segment buffers ------------------------------------
__global__ void k_init() {
    int t = blockIdx.x * blockDim.x + threadIdx.x;
    if (t < NN * DD) g_h2[t] = 0.0f;
    if (t < NN * HH) {
        g_mmax[t] = fenc(__int_as_float(0xff800000)); // -inf
        g_ssum[t] = 0.0f;
    }
}

// ---------------- K1: distances, RBF filter GEMM, cutoff, q = LN(W*h1[dst]+t)
__global__ __launch_bounds__(256) void k_edge_filter(
    const float* __restrict__ pos, const float* __restrict__ h1,
    const float* __restrict__ t_in, const float* __restrict__ fw,
    const float* __restrict__ fb, const float* __restrict__ lng,
    const float* __restrict__ lnb, const int* __restrict__ src,
    const int* __restrict__ dst, float* __restrict__ outW)
{
    extern __shared__ float sm[];
    float* s_fw = sm;                 // [GG][DD] 32KB
    float* s_f2 = sm + GG * DD;       // [64][GG] 16KB
    __shared__ float s_r[64], s_C[64];
    __shared__ int s_dst[64];

    const int tid = threadIdx.x;
    const int base = blockIdx.x * 64;

    for (int i = tid; i < GG * DD / 4; i += 256)
        ((float4*)s_fw)[i] = ((const float4*)fw)[i];

    if (tid < 64) {
        int e = base + tid;
        int sI = src[e], dI = dst[e];
        float dx = pos[dI * 3 + 0] - pos[sI * 3 + 0];
        float dy = pos[dI * 3 + 1] - pos[sI * 3 + 1];
        float dz = pos[dI * 3 + 2] - pos[sI * 3 + 2];
        float r = sqrtf(dx * dx + dy * dy + dz * dz);
        float C = (r < 5.0f) ? 0.5f * (cospif(r * 0.2f) + 1.0f) : 0.0f;
        s_r[tid] = r; s_C[tid] = C; s_dst[tid] = dI;
        g_C[e] = C;
    }
    __syncthreads();

    const float alpha = -0.5f / (WIDTHF * WIDTHF);
    for (int idx = tid; idx < 64 * GG; idx += 256) {
        int e = idx >> 6, g = idx & 63;
        float diff = s_r[e] - (float)g * WIDTHF;
        float f2 = (fabsf(diff) < 8.0f * WIDTHF)
                       ? 2.0f * __expf(alpha * diff * diff) - 1.0f
                       : -1.0f;
        s_f2[e * GG + g] = f2;
    }
    __syncthreads();

    const int tx = tid & 31, ty = tid >> 5;
    float4 fbv = ((const float4*)fb)[tx];
    float4 acc[8];
#pragma unroll
    for (int i = 0; i < 8; i++) acc[i] = fbv;

#pragma unroll 4
    for (int g4 = 0; g4 < GG / 4; g4++) {
        float4 b0 = *(const float4*)&s_fw[(4 * g4 + 0) * DD + tx * 4];
        float4 b1 = *(const float4*)&s_fw[(4 * g4 + 1) * DD + tx * 4];
        float4 b2 = *(const float4*)&s_fw[(4 * g4 + 2) * DD + tx * 4];
        float4 b3 = *(const float4*)&s_fw[(4 * g4 + 3) * DD + tx * 4];
#pragma unroll
        for (int i = 0; i < 8; i++) {
            float4 a = *(const float4*)&s_f2[(ty * 8 + i) * GG + 4 * g4];
            acc[i].x += a.x * b0.x + a.y * b1.x + a.z * b2.x + a.w * b3.x;
            acc[i].y += a.x * b0.y + a.y * b1.y + a.z * b2.y + a.w * b3.y;
            acc[i].z += a.x * b0.z + a.y * b1.z + a.z * b2.z + a.w * b3.z;
            acc[i].w += a.x * b0.w + a.y * b1.w + a.z * b2.w + a.w * b3.w;
        }
    }

    float4 gv = ((const float4*)lng)[tx];
    float4 bv = ((const float4*)lnb)[tx];
#pragma unroll
    for (int i = 0; i < 8; i++) {
        int el = ty * 8 + i;
        int e = base + el;
        float C = s_C[el];
        float4 w = acc[i];
        w.x *= C; w.y *= C; w.z *= C; w.w *= C;
        ((float4*)outW)[(size_t)e * 32 + tx] = w;

        int dI = s_dst[el];
        float4 hv = ((const float4*)h1)[(size_t)dI * 32 + tx];
        float4 tv = ((const float4*)t_in)[(size_t)e * 32 + tx];
        float4 q;
        q.x = w.x * hv.x + tv.x;
        q.y = w.y * hv.y + tv.y;
        q.z = w.z * hv.z + tv.z;
        q.w = w.w * hv.w + tv.w;

        float ps = q.x + q.y + q.z + q.w;
        float pss = q.x * q.x + q.y * q.y + q.z * q.z + q.w * q.w;
#pragma unroll
        for (int o = 16; o; o >>= 1) {
            ps += __shfl_xor_sync(0xffffffffu, ps, o);
            pss += __shfl_xor_sync(0xffffffffu, pss, o);
        }
        float mu = ps * (1.0f / 128.0f);
        float var = pss * (1.0f / 128.0f) - mu * mu;
        float rstd = rsqrtf(var + LN_EPS);
        q.x = (q.x - mu) * rstd * gv.x + bv.x;
        q.y = (q.y - mu) * rstd * gv.y + bv.y;
        q.z = (q.z - mu) * rstd * gv.z + bv.z;
        q.w = (q.w - mu) * rstd * gv.w + bv.w;
        ((float4*)g_q)[(size_t)e * 32 + tx] = q;
    }
}

// SIMT GEMM inner: out[64 rows x 128] = s_A[64x128] @ s_B[128x128]
__device__ __forceinline__ void gemm_tile(const float* s_A, const float* s_B,
                                          float4 acc[8], int tx, int ty)
{
#pragma unroll 4
    for (int k4 = 0; k4 < DD / 4; k4++) {
        float4 b0 = *(const float4*)&s_B[(4 * k4 + 0) * DD + tx * 4];
        float4 b1 = *(const float4*)&s_B[(4 * k4 + 1) * DD + tx * 4];
        float4 b2 = *(const float4*)&s_B[(4 * k4 + 2) * DD + tx * 4];
        float4 b3 = *(const float4*)&s_B[(4 * k4 + 3) * DD + tx * 4];
#pragma unroll
        for (int i = 0; i < 8; i++) {
            float4 a = *(const float4*)&s_A[(ty * 8 + i) * DD + 4 * k4];
            acc[i].x += a.x * b0.x + a.y * b1.x + a.z * b2.x + a.w * b3.x;
            acc[i].y += a.x * b0.y + a.y * b1.y + a.z * b2.y + a.w * b3.y;
            acc[i].z += a.x * b0.z + a.y * b1.z + a.z * b2.z + a.w * b3.z;
            acc[i].w += a.x * b0.w + a.y * b1.w + a.z * b2.w + a.w * b3.w;
        }
    }
}

// ---------------- K2: q_vec = q[q_id] @ Wq  (node-level) -------------------
__global__ __launch_bounds__(256) void k_qvec(const float* __restrict__ Wq,
                                              const int* __restrict__ q_id)
{
    extern __shared__ float sm[];
    float* s_A = sm;
    float* s_B = sm + 64 * DD;
    const int tid = threadIdx.x;
    const int base = blockIdx.x * 64;

    for (int i = tid; i < DD * DD / 4; i += 256)
        ((float4*)s_B)[i] = ((const float4*)Wq)[i];
    for (int i = tid; i < 64 * DD / 4; i += 256) {
        int row = i >> 5, c4 = i & 31;
        int gr = base + row;
        float4 vv = make_float4(0.f, 0.f, 0.f, 0.f);
        if (gr < NN) {
            int ar = q_id[gr];
            vv = ((const float4*)g_q)[(size_t)ar * 32 + c4];
        }
        ((float4*)s_A)[i] = vv;
    }
    __syncthreads();

    const int tx = tid & 31, ty = tid >> 5;
    float4 acc[8];
#pragma unroll
    for (int i = 0; i < 8; i++) acc[i] = make_float4(0.f, 0.f, 0.f, 0.f);
    gemm_tile(s_A, s_B, acc, tx, ty);
#pragma unroll
    for (int i = 0; i < 8; i++) {
        int gr = base + ty * 8 + i;
        if (gr < NN) ((float4*)g_qvec)[(size_t)gr * 32 + tx] = acc[i];
    }
}

// ---------------- K3 (tensor): fused k|v = q @ [Wk|Wv] ---------------------
// Block: 512 threads (16 warps, warpM 0..3 x warpG 0..3).
// Tile M=128 edges, N=256 (cols 0..127 = k half, 128..255 = v half), K=128.
// warpG 0..1 -> k half (logits epilogue); warpG 2..3 -> v half (store).
#define QPAD 132   // A-tile stride (conflict-free A fragment loads)
#define BPAD 264   // fused B-tile stride (conflict-free B fragment loads)

__device__ __forceinline__ void mma_tf32(float c[4], const unsigned a[4],
                                         const unsigned b[2])
{
    asm volatile(
        "mma.sync.aligned.m16n8k8.row.col.f32.tf32.tf32.f32 "
        "{%0,%1,%2,%3}, {%4,%5,%6,%7}, {%8,%9}, {%0,%1,%2,%3};"
        : "+f"(c[0]), "+f"(c[1]), "+f"(c[2]), "+f"(c[3])
        : "r"(a[0]), "r"(a[1]), "r"(a[2]), "r"(a[3]), "r"(b[0]), "r"(b[1]));
}

__global__ __launch_bounds__(512) void k_kv(const float* __restrict__ Wk,
                                            const float* __restrict__ Wv,
                                            const int* __restrict__ src)
{
    extern __shared__ float sm[];
    float* s_q = sm;               // [128][QPAD]  67.6KB
    float* s_B = sm + 128 * QPAD;  // [128][BPAD] 135.2KB  ([Wk | Wv])
    __shared__ int s_src[128];

    const int tid = threadIdx.x;
    const int lane = tid & 31;
    const int wid = tid >> 5;
    const int warpM = wid & 3;       // 4 warps along M (32 rows each)
    const int warpG = wid >> 2;      // 4 warps along fused N (64 cols each)
    const int base = blockIdx.x * 128;

    // stage q tile (tf32-rounded) + src
    for (int i = tid; i < 128 * 32; i += 512) {
        int row = i >> 5, c4 = i & 31;
        float4 v = ((const float4*)g_q)[(size_t)(base + row) * 32 + c4];
        v.x = tf32r(v.x); v.y = tf32r(v.y); v.z = tf32r(v.z); v.w = tf32r(v.w);
        *(float4*)&s_q[row * QPAD + c4 * 4] = v;
    }
    if (tid < 128) s_src[tid] = src[base + tid];
    // stage Wk into cols [0,128), Wv into cols [128,256)
    for (int i = tid; i < 128 * 32; i += 512) {
        int row = i >> 5, c4 = i & 31;
        float4 v = ((const float4*)Wk)[i];
        v.x = tf32r(v.x); v.y = tf32r(v.y); v.z = tf32r(v.z); v.w = tf32r(v.w);
        *(float4*)&s_B[row * BPAD + c4 * 4] = v;
    }
    for (int i = tid; i < 128 * 32; i += 512) {
        int row = i >> 5, c4 = i & 31;
        float4 v = ((const float4*)Wv)[i];
        v.x = tf32r(v.x); v.y = tf32r(v.y); v.z = tf32r(v.z); v.w = tf32r(v.w);
        *(float4*)&s_B[row * BPAD + 128 + c4 * 4] = v;
    }
    __syncthreads();

    const int rA = warpM * 32 + (lane >> 2);   // A fragment base row
    const int cN = warpG * 64 + (lane >> 2);   // B fragment base col (fused)
    const int kA = lane & 3;

    float c[2][8][4];
#pragma unroll
    for (int mt = 0; mt < 2; mt++)
#pragma unroll
        for (int nt = 0; nt < 8; nt++)
#pragma unroll
            for (int j = 0; j < 4; j++) c[mt][nt][j] = 0.0f;

    // ---- single fused pass: [k|v] = q @ [Wk|Wv] ----
#pragma unroll 2
    for (int ks = 0; ks < 16; ks++) {
        int k0 = ks * 8;
        unsigned a[2][4], b[8][2];
#pragma unroll
        for (int mt = 0; mt < 2; mt++) {
            const float* ap = &s_q[(rA + mt * 16) * QPAD + k0 + kA];
            a[mt][0] = __float_as_uint(ap[0]);
            a[mt][1] = __float_as_uint(ap[8 * QPAD]);
            a[mt][2] = __float_as_uint(ap[4]);
            a[mt][3] = __float_as_uint(ap[8 * QPAD + 4]);
        }
#pragma unroll
        for (int nt = 0; nt < 8; nt++) {
            const float* bp = &s_B[(k0 + kA) * BPAD + cN + nt * 8];
            b[nt][0] = __float_as_uint(bp[0]);
            b[nt][1] = __float_as_uint(bp[4 * BPAD]);
        }
#pragma unroll
        for (int mt = 0; mt < 2; mt++)
#pragma unroll
            for (int nt = 0; nt < 8; nt++)
                mma_tf32(c[mt][nt], a[mt], b[nt]);
    }

    if (warpG < 2) {
        // ---- epilogue (k half): logits via per-head dot with q_vec[src] ----
        float ph[2][2][4];   // [mt][rowhalf][local head]
#pragma unroll
        for (int mt = 0; mt < 2; mt++)
#pragma unroll
            for (int hf = 0; hf < 2; hf++)
#pragma unroll
                for (int h = 0; h < 4; h++) ph[mt][hf][h] = 0.0f;

        const int col0base = warpG * 64 + 2 * (lane & 3);
#pragma unroll
        for (int mt = 0; mt < 2; mt++) {
#pragma unroll
            for (int hf = 0; hf < 2; hf++) {
                int r = rA + mt * 16 + hf * 8;
                int sI = s_src[r];
                const float* qv = &g_qvec[(size_t)sI * DD];
#pragma unroll
                for (int nt = 0; nt < 8; nt++) {
                    float2 q2 = *(const float2*)&qv[col0base + nt * 8];
                    ph[mt][hf][nt >> 1] +=
                        c[mt][nt][2 * hf] * q2.x + c[mt][nt][2 * hf + 1] * q2.y;
                }
            }
        }
#pragma unroll
        for (int mt = 0; mt < 2; mt++)
#pragma unroll
            for (int hf = 0; hf < 2; hf++)
#pragma unroll
                for (int h = 0; h < 4; h++) {
                    float v = ph[mt][hf][h];
                    v += __shfl_xor_sync(0xffffffffu, v, 1);
                    v += __shfl_xor_sync(0xffffffffu, v, 2);
                    ph[mt][hf][h] = v;
                }
        int hl = lane & 3;
        int head = warpG * 4 + hl;
#pragma unroll
        for (int mt = 0; mt < 2; mt++)
#pragma unroll
            for (int hf = 0; hf < 2; hf++) {
                int r = rA + mt * 16 + hf * 8;
                int e = base + r;
                int sI = s_src[r];
                float logit = ph[mt][hf][hl] * 0.25f;  // 1/sqrt(P=16)
                g_logit[(size_t)e * HH + head] = logit;
                atomicMax(&g_mmax[(size_t)sI * HH + head], fenc(logit));
            }
    } else {
        // ---- epilogue (v half): store v fragments ----
        const int col0 = (warpG - 2) * 64 + 2 * (lane & 3);
#pragma unroll
        for (int mt = 0; mt < 2; mt++) {
            int r = rA + mt * 16;
#pragma unroll
            for (int nt = 0; nt < 8; nt++) {
                int cc = col0 + nt * 8;
                *(float2*)&g_v[(size_t)(base + r) * DD + cc] =
                    make_float2(c[mt][nt][0], c[mt][nt][1]);
                *(float2*)&g_v[(size_t)(base + r + 8) * DD + cc] =
                    make_float2(c[mt][nt][2], c[mt][nt][3]);
            }
        }
    }
}

// ---------------- K4: a = exp(logit - m[src]) * C ; segment-sum ------------
__global__ void k_soft(const int* __restrict__ src) {
    int t = blockIdx.x * blockDim.x + threadIdx.x;
    if (t >= EE * HH) return;
    int e = t >> 3, h = t & 7;
    int sI = src[e];
    float m = fdec(g_mmax[(size_t)sI * HH + h]);
    float a = __expf(g_logit[t] - m) * g_C[e];
    g_logit[t] = a;
    atomicAdd(&g_ssum[(size_t)sI * HH + h], a);
}

// ---------------- K5: he = v * att ; scatter-add to h2[src] ----------------
__global__ __launch_bounds__(256) void k_scatter(const int* __restrict__ src) {
    const int tid = threadIdx.x;
    const int tx = tid & 31, wid = tid >> 5;
    int e = blockIdx.x * 8 + wid;
    int sI = __ldg(&src[e]);
    int h = tx >> 2;
    float att = g_logit[(size_t)e * HH + h] / g_ssum[(size_t)sI * HH + h];
    float4 v = ((const float4*)g_v)[(size_t)e * 32 + tx];
    float* dp = &g_h2[(size_t)sI * DD + tx * 4];
    atomicAdd(dp + 0, v.x * att);
    atomicAdd(dp + 1, v.y * att);
    atomicAdd(dp + 2, v.z * att);
    atomicAdd(dp + 3, v.w * att);
}

// ---------------- K6: m_agg = h2 @ Wo --------------------------------------
__global__ __launch_bounds__(256) void k_out(const float* __restrict__ Wo,
                                             float* __restrict__ outM)
{
    extern __shared__ float sm[];
    float* s_A = sm;
    float* s_B = sm + 64 * DD;
    const int tid = threadIdx.x;
    const int base = blockIdx.x * 64;

    for (int i = tid; i < DD * DD / 4; i += 256)
        ((float4*)s_B)[i] = ((const float4*)Wo)[i];
    for (int i = tid; i < 64 * DD / 4; i += 256) {
        int row = i >> 5, c4 = i & 31;
        int gr = base + row;
        float4 vv = make_float4(0.f, 0.f, 0.f, 0.f);
        if (gr < NN) vv = ((const float4*)g_h2)[(size_t)gr * 32 + c4];
        ((float4*)s_A)[i] = vv;
    }
    __syncthreads();

    const int tx = tid & 31, ty = tid >> 5;
    float4 acc[8];
#pragma unroll
    for (int i = 0; i < 8; i++) acc[i] = make_float4(0.f, 0.f, 0.f, 0.f);
    gemm_tile(s_A, s_B, acc, tx, ty);
#pragma unroll
    for (int i = 0; i < 8; i++) {
        int gr = base + ty * 8 + i;
        if (gr < NN) ((float4*)outM)[(size_t)gr * 32 + tx] = acc[i];
    }
}

// ---------------------------------------------------------------------------
extern "C" void kernel_launch(void* const* d_in, const int* in_sizes, int n_in,
                              void* d_out, int out_size)
{
    const float* pos  = (const float*)d_in[0];
    const float* h1   = (const float*)d_in[1];
    const float* t_in = (const float*)d_in[2];
    const float* fw   = (const float*)d_in[3];
    const float* fb   = (const float*)d_in[4];
    const float* lng  = (const float*)d_in[5];
    const float* lnb  = (const float*)d_in[6];
    const float* Wq   = (const float*)d_in[7];
    const float* Wk   = (const float*)d_in[8];
    const float* Wv   = (const float*)d_in[9];
    const float* Wo   = (const float*)d_in[10];
    const int* src    = (const int*)d_in[11];
    const int* dst    = (const int*)d_in[12];
    const int* q_id   = (const int*)d_in[13];

    float* outM = (float*)d_out;                       // [N, D]
    float* outW = outM + (size_t)NN * DD;              // [E, D]

    const int smem_filter = (GG * DD + 64 * GG) * sizeof(float);       // 48KB
    const int smem_gemm   = (64 * DD + DD * DD) * sizeof(float);       // 96KB
    const int smem_kv     = (128 * QPAD + 128 * BPAD) * sizeof(float); // ~203KB
    cudaFuncSetAttribute(k_edge_filter, cudaFuncAttributeMaxDynamicSharedMemorySize, smem_filter);
    cudaFuncSetAttribute(k_qvec, cudaFuncAttributeMaxDynamicSharedMemorySize, smem_gemm);
    cudaFuncSetAttribute(k_kv,   cudaFuncAttributeMaxDynamicSharedMemorySize, smem_kv);
    cudaFuncSetAttribute(k_out,  cudaFuncAttributeMaxDynamicSharedMemorySize, smem_gemm);

    k_init<<<(NN * DD + 255) / 256, 256>>>();
    k_edge_filter<<<EE / 64, 256, smem_filter>>>(pos, h1, t_in, fw, fb, lng, lnb,
                                                 src, dst, outW);
    k_qvec<<<(NN + 63) / 64, 256, smem_gemm>>>(Wq, q_id);
    k_kv<<<EE / 128, 512, smem_kv>>>(Wk, Wv, src);
    k_soft<<<(EE * HH + 255) / 256, 256>>>(src);
    k_scatter<<<EE / 8, 256>>>(src);
    k_out<<<(NN + 63) / 64, 256, smem_gemm>>>(Wo, outM);
}